// round 16
// baseline (speedup 1.0000x reference)
#include <cuda_runtime.h>
#include <cuda_bf16.h>
#include <cstdint>

#define N_NODES 100000
#define N_EDGES 1200000
#define B_GR    512
#define HIDDIM  64
#define KSEL    3

#define SCAN_BLK 512
#define NBLK_SCAN ((N_NODES + SCAN_BLK - 1) / SCAN_BLK)   // 196

// ---------------- scratch (device globals; no allocation allowed) ----------------
__device__ int   g_odeg[N_NODES];
__device__ int   g_ideg[N_NODES];
__device__ int   g_start[N_NODES];     // CSR row start (by dst)
__device__ int   g_cursor[N_NODES];
__device__ int   g_blksum[NBLK_SCAN];
__device__ int   g_csr_src[N_EDGES];
__device__ float g_norm_s[N_NODES];
__device__ float g_norm_d[N_NODES];
__device__ __align__(256) float g_h [N_NODES * HIDDIM];   // layer-1 output
__device__ __align__(256) float g_h2[N_NODES * HIDDIM];   // layer-2 output
__device__ float g_key[N_NODES];
__device__ int   g_sel[B_GR * KSEL];

// ---------------- CSR build ----------------
__global__ void k_zero_int() {
    int i = blockIdx.x * blockDim.x + threadIdx.x;
    if (i < N_NODES) { g_odeg[i] = 0; g_ideg[i] = 0; }
}

__global__ void k_deg(const int* __restrict__ src, const int* __restrict__ dst) {
    int e = blockIdx.x * blockDim.x + threadIdx.x;
    if (e < N_EDGES) {
        atomicAdd(&g_odeg[src[e]], 1);
        atomicAdd(&g_ideg[dst[e]], 1);
    }
}

// per-block inclusive scan of in_deg -> g_start, block totals -> g_blksum
__global__ void k_scan1() {
    __shared__ int wsum[16];
    int i = blockIdx.x * SCAN_BLK + threadIdx.x;
    int lane = threadIdx.x & 31, w = threadIdx.x >> 5;
    int v = (i < N_NODES) ? g_ideg[i] : 0;
    int x = v;
#pragma unroll
    for (int off = 1; off < 32; off <<= 1) {
        int n = __shfl_up_sync(0xffffffffu, x, off);
        if (lane >= off) x += n;
    }
    if (lane == 31) wsum[w] = x;
    __syncthreads();
    if (w == 0) {
        int s = (lane < 16) ? wsum[lane] : 0;
#pragma unroll
        for (int off = 1; off < 16; off <<= 1) {
            int n = __shfl_up_sync(0xffffffffu, s, off);
            if (lane >= off) s += n;
        }
        if (lane < 16) wsum[lane] = s;
    }
    __syncthreads();
    int add = (w > 0) ? wsum[w - 1] : 0;
    int incl = x + add;
    if (i < N_NODES) g_start[i] = incl;                 // inclusive, intra-block
    if (threadIdx.x == SCAN_BLK - 1) g_blksum[blockIdx.x] = incl;
}

// exclusive scan of 196 block sums — single warp, sequential 32-chunks
__global__ void k_scan2w() {
    int lane = threadIdx.x;
    int carry = 0;
    for (int base = 0; base < NBLK_SCAN; base += 32) {
        int i = base + lane;
        int v = (i < NBLK_SCAN) ? g_blksum[i] : 0;
        int x = v;
#pragma unroll
        for (int off = 1; off < 32; off <<= 1) {
            int n = __shfl_up_sync(0xffffffffu, x, off);
            if (lane >= off) x += n;
        }
        if (i < NBLK_SCAN) g_blksum[i] = carry + x - v;   // exclusive
        carry += __shfl_sync(0xffffffffu, x, 31);
    }
}

// start = inclusive - deg + block offset; cursor = start; norms too (fused)
__global__ void k_scan3() {
    int i = blockIdx.x * blockDim.x + threadIdx.x;
    if (i < N_NODES) {
        int ideg = g_ideg[i];
        int s = g_start[i] - ideg + g_blksum[i / SCAN_BLK];
        g_start[i]  = s;
        g_cursor[i] = s;
        g_norm_s[i] = rsqrtf(fmaxf((float)g_odeg[i], 1.f));
        g_norm_d[i] = rsqrtf(fmaxf((float)ideg, 1.f));
    }
}

__global__ void k_fill(const int* __restrict__ src, const int* __restrict__ dst) {
    int e = blockIdx.x * blockDim.x + threadIdx.x;
    if (e < N_EDGES) {
        int pos = atomicAdd(&g_cursor[dst[e]], 1);
        g_csr_src[pos] = src[e];
    }
}

// ---------------- fused GCN layer: h_out = relu(norm_d * ((Σ_src x*norm_s) @ W) + b) ----
// One block = 64 dst nodes.
// Phase 1 (gather): 16 lanes per node (float4 cols), 2 nodes/warp, 16 nodes per pass,
//   4 passes; norm_s folded into the accumulate FMA via shuffle broadcast.
//   Agg rows land in smem (stride 66 floats).
// Phase 2 (gemm): 16 groups x 16 lanes; group g computes local rows {r*16+g};
//   bank-conflict-free broadcasts (2g+i mod 32 distinct across groups).
// layer==0: read xin (features), write g_h. layer==1: read g_h, write g_h2 + keys.
__global__ void __launch_bounds__(256) k_layer(const float* __restrict__ xin,
                                               const float* __restrict__ W,
                                               const float* __restrict__ bvec,
                                               int layer) {
    __shared__ __align__(16) float Wsm[HIDDIM * HIDDIM];   // 16 KB
    __shared__ float Asm[64 * 66];                          // ~16.9 KB

    int tid = threadIdx.x;
    const float4* x4 = (layer == 0) ? (const float4*)xin : (const float4*)g_h;
    float* outh = (layer == 0) ? g_h : g_h2;

    // stage W
    {
        const float4* Wg = (const float4*)W;
        float4* Ws = (float4*)Wsm;
        for (int i = tid; i < HIDDIM * HIDDIM / 4; i += 256) Ws[i] = Wg[i];
    }

    int lane = tid & 31;
    int ql   = lane & 15;
    int warp = tid >> 5;
    int nodeBase = blockIdx.x * 64;

    // ---- phase 1: gather ----
    for (int sub = 0; sub < 4; sub++) {
        int local = sub * 16 + warp * 2 + ((lane >> 4) & 1);
        int node = nodeBase + local;
        int deg = 0, start = 0;
        if (node < N_NODES) { deg = g_ideg[node]; start = g_start[node]; }
        int degmax = max(deg, __shfl_xor_sync(0xffffffffu, deg, 16));

        float4 acc = make_float4(0.f, 0.f, 0.f, 0.f);
        for (int c = 0; c < degmax; c += 16) {
            int idx = c + ql;
            int s = -1; float ns = 0.f;
            if (idx < deg) {
                s  = __ldg(&g_csr_src[start + idx]);
                ns = __ldg(&g_norm_s[s]);
            }
#pragma unroll 4
            for (int j = 0; j < 16; j++) {
                int srcl = (lane & 16) | j;
                int   sj  = __shfl_sync(0xffffffffu, s,  srcl);
                float nsj = __shfl_sync(0xffffffffu, ns, srcl);
                if (sj >= 0) {
                    float4 v = __ldg(&x4[sj * 16 + ql]);
                    acc.x += nsj * v.x; acc.y += nsj * v.y;
                    acc.z += nsj * v.z; acc.w += nsj * v.w;
                }
            }
        }
        float* ap = &Asm[local * 66 + ql * 4];
        ap[0] = acc.x; ap[1] = acc.y; ap[2] = acc.z; ap[3] = acc.w;
    }
    __syncthreads();

    // ---- phase 2: 64x64x64 gemm + epilogue ----
    int g = tid >> 4, q = tid & 15;
    float4 acc[4];
#pragma unroll
    for (int r = 0; r < 4; r++) acc[r] = make_float4(0.f, 0.f, 0.f, 0.f);

    const float4* W4 = (const float4*)Wsm;
#pragma unroll 8
    for (int i = 0; i < HIDDIM; i++) {
        float4 w = W4[i * 16 + q];
#pragma unroll
        for (int r = 0; r < 4; r++) {
            float h = Asm[(r * 16 + g) * 66 + i];      // conflict-free broadcast
            acc[r].x += h * w.x; acc[r].y += h * w.y;
            acc[r].z += h * w.z; acc[r].w += h * w.w;
        }
    }

    float4 bb = __ldg(&((const float4*)bvec)[q]);
#pragma unroll
    for (int r = 0; r < 4; r++) {
        int node = nodeBase + r * 16 + g;
        bool valid = node < N_NODES;
        float nd = valid ? g_norm_d[node] : 1.f;
        float4 h;
        h.x = fmaxf(acc[r].x * nd + bb.x, 0.f);
        h.y = fmaxf(acc[r].y * nd + bb.y, 0.f);
        h.z = fmaxf(acc[r].z * nd + bb.z, 0.f);
        h.w = fmaxf(acc[r].w * nd + bb.w, 0.f);
        if (valid) ((float4*)outh)[node * 16 + q] = h;

        if (layer == 1) {
            float v = fmaxf(fmaxf(h.x, h.y), fmaxf(h.z, h.w));
#pragma unroll
            for (int off = 8; off > 0; off >>= 1)
                v = fmaxf(v, __shfl_xor_sync(0xffffffffu, v, off));
            if (valid && q == 0) g_key[node] = v;
        }
    }
}

// ---------------- top-3 per graph (key desc, index asc tie-break) ----------------
__global__ void k_select(const int* __restrict__ gid) {
    if (threadIdx.x != 0) return;
    int g = blockIdx.x;
    int a = 0, b = N_NODES;
    while (a < b) { int mid = (a + b) >> 1; if (gid[mid] < g) a = mid + 1; else b = mid; }
    int lo = a;
    a = lo; b = N_NODES;
    while (a < b) { int mid = (a + b) >> 1; if (gid[mid] < g + 1) a = mid + 1; else b = mid; }
    int hi = a;

    float k0 = -1.f, k1 = -1.f, k2 = -1.f;
    int   i0 = -1,   i1 = -1,   i2 = -1;
    for (int idx = lo; idx < hi; idx++) {
        float kk = g_key[idx];
        if (kk > k0)      { k2 = k1; i2 = i1; k1 = k0; i1 = i0; k0 = kk; i0 = idx; }
        else if (kk > k1) { k2 = k1; i2 = i1; k1 = kk; i1 = idx; }
        else if (kk > k2) { k2 = kk; i2 = idx; }
    }
    g_sel[g * 3 + 0] = i0;
    g_sel[g * 3 + 1] = i1;
    g_sel[g * 3 + 2] = i2;
}

// ---------------- per-graph: sort 3 rows, conv-dot, classify (exact fp32) ----------------
__global__ void k_final(const float* __restrict__ cw, const float* __restrict__ cb,
                        const float* __restrict__ Wc, const float* __restrict__ bc,
                        float* __restrict__ out) {
    __shared__ float p[192];
    __shared__ float y[64];
    int g = blockIdx.x;
    int tid = threadIdx.x;
    int seg = tid / 64, t = tid % 64;

    int node = g_sel[g * 3 + seg];
    p[seg * 64 + t] = (node >= 0) ? g_h2[node * 64 + t] : 0.f;
    __syncthreads();

    for (int k2 = 2; k2 <= 64; k2 <<= 1) {
        for (int j = k2 >> 1; j > 0; j >>= 1) {
            int ixj = t ^ j;
            if (ixj > t) {
                float a = p[seg * 64 + t], b = p[seg * 64 + ixj];
                bool up = ((t & k2) == 0);
                if ((a > b) == up) { p[seg * 64 + t] = b; p[seg * 64 + ixj] = a; }
            }
            __syncthreads();
        }
    }

    if (tid < 64) {
        float acc = cb[tid];
        const float* cwo = cw + tid * 192;
#pragma unroll 8
        for (int j = 0; j < 192; j++) acc += p[j] * cwo[j];
        y[tid] = fmaxf(acc, 0.f);
    }
    __syncthreads();

    if (tid < 10) {
        float acc = bc[tid];
#pragma unroll 8
        for (int o = 0; o < 64; o++) acc += y[o] * Wc[o * 10 + tid];
        out[g * 10 + tid] = acc;
    }
}

// ---------------- launch ----------------
extern "C" void kernel_launch(void* const* d_in, const int* in_sizes, int n_in,
                              void* d_out, int out_size) {
    const float* features = (const float*)d_in[0];
    const int*   esrc     = (const int*)  d_in[1];
    const int*   edst     = (const int*)  d_in[2];
    const int*   gid      = (const int*)  d_in[3];

    int base = (n_in >= 13) ? 5 : 4;
    const float* W1 = (const float*)d_in[base + 0];
    const float* b1 = (const float*)d_in[base + 1];
    const float* W2 = (const float*)d_in[base + 2];
    const float* b2 = (const float*)d_in[base + 3];
    const float* cw = (const float*)d_in[base + 4];
    const float* cb = (const float*)d_in[base + 5];
    const float* Wc = (const float*)d_in[base + 6];
    const float* bc = (const float*)d_in[base + 7];
    float* out = (float*)d_out;

    const int TB = 256;
    int gN  = (N_NODES + TB - 1) / TB;
    int gE  = (N_EDGES + TB - 1) / TB;
    int gL  = (N_NODES + 63) / 64;      // 64 nodes per fused-layer block

    // CSR build (shared by both layers) + norms
    k_zero_int<<<gN, TB>>>();
    k_deg<<<gE, TB>>>(esrc, edst);
    k_scan1<<<NBLK_SCAN, SCAN_BLK>>>();
    k_scan2w<<<1, 32>>>();
    k_scan3<<<gN, TB>>>();
    k_fill<<<gE, TB>>>(esrc, edst);

    // fused layers (gather + gemm + relu [+ key])
    k_layer<<<gL, TB>>>(features, W1, b1, 0);
    k_layer<<<gL, TB>>>(nullptr,  W2, b2, 1);

    // sort-pool + conv + classifier
    k_select<<<B_GR, 32>>>(gid);
    k_final<<<B_GR, 192>>>(cw, cb, Wc, bc, out);
}